// round 11
// baseline (speedup 1.0000x reference)
#include <cuda_runtime.h>
#include <cuda_bf16.h>

// Shape fixed for this dataset entry
#define NN 8
#define LL 8192
#define SS 8192
#define HH 8
#define RS 256              // floats per token row (H*D)
#define NH 64               // N*H

#define PART 1056           // 1024 KV (f32x2-pair layout) + 32 Ksum
#define P2C 16              // phase2 L-chunks

// phase1: 64 chunks/head, 128 tokens per 64-thread group, 16 stages of 8 tokens
#define P1CH 64
#define KROWF 36            // k stage row stride (floats), 144B: quad-rotating banks
#define KBUF  (8*KROWF)     // 288
#define VROWF 100           // v stage row stride (floats), skewed dup layout
#define VBUF  (8*VROWF)     // 800
#define GSM   (2*KBUF + 2*VBUF)   // 2176 floats per group

// Deterministic scratch
__device__ __align__(16) float g_part[P1CH * NH * PART];   // ~17.3 MB
__device__ __align__(16) float g_red [NH * PART];

typedef unsigned long long u64;

__device__ __forceinline__ u64 fma2(u64 a, u64 b, u64 c) {
    u64 d;
    asm("fma.rn.f32x2 %0, %1, %2, %3;" : "=l"(d) : "l"(a), "l"(b), "l"(c));
    return d;
}
__device__ __forceinline__ float2 unp(u64 a) {
    float2 r;
    asm("mov.b64 {%0, %1}, %2;" : "=f"(r.x), "=f"(r.y) : "l"(a));
    return r;
}
__device__ __forceinline__ float elu1(float x) {
    return x > 0.0f ? x + 1.0f : __expf(x);   // elu(x)+1 = exp(x) for x<=0
}
__device__ __forceinline__ void gbar(int id) {   // 64-thread group barrier
    asm volatile("bar.sync %0, 64;" :: "r"(id) : "memory");
}

// ---------------------------------------------------------------------------
// Phase 1 (register-blocked): 4 independent 64-thread groups per block; each
// group owns a 128-token chunk and a full 32x32 KV tile, thread = 4x4 block
// (d = 4ti.., v = 4tj..). Per token per thread: 1 LDS.128 (k quad, multicast)
// + 4 LDS.64 (pre-duplicated v pairs, conflict-free skew) + 8 FFMA2.
// Double-buffered 8-token stages, one named barrier per stage.
// v skew: dup-pair of v at float offset 2v + 2*(v>>2)*2 -> 12*tj+2j, banks
// (12tj+2j) mod 32 distinct for tj=0..7.
// Partial layout (unchanged): float p = jj*64 + 2v + e <-> KV[2jj+e][v];
// p = 1024+d -> Ksum[d].
// ---------------------------------------------------------------------------
__global__ void __launch_bounds__(256)
phase1_kernel(const float* __restrict__ K, const float* __restrict__ V)
{
    __shared__ __align__(16) float smem[4][GSM];

    const int tid = threadIdx.x;
    const int g   = tid >> 6;            // group 0..3
    const int g64 = tid & 63;
    const int tok_slot = g64 >> 3;       // staging: token slot 0..7
    const int quad     = g64 & 7;        // staging: 4-float quad 0..7
    const int ti = g64 >> 3;             // compute: d-block 0..7 (d = 4ti..)
    const int tj = g64 & 7;              // compute: v-block 0..7 (v = 4tj..)

    const int bx = blockIdx.x;
    const int nh = bx >> 4;
    const int chunk = ((bx & 15) << 2) + g;   // 0..63
    const int n = nh >> 3, h = nh & 7;

    float* sm = smem[g];
    float* skb[2] = { sm, sm + KBUF };
    float* svb[2] = { sm + 2 * KBUF, sm + 2 * KBUF + VBUF };

    // staging source: token row = chunk*128 + stage*8 + tok_slot, cols quad*4..
    const size_t rowbase = ((size_t)n * SS + (size_t)chunk * 128 + tok_slot) * RS
                         + h * 32 + quad * 4;
    const float4* Kst = (const float4*)(K + rowbase);
    const float4* Vst = (const float4*)(V + rowbase);
    // 8 rows per stage = 8*RS floats = 512 float4

    u64 acc[2][4];
    #pragma unroll
    for (int p = 0; p < 2; p++)
        #pragma unroll
        for (int j = 0; j < 4; j++) acc[p][j] = 0ULL;
    float4 ksum4 = make_float4(0.f, 0.f, 0.f, 0.f);

    float4 kq = Kst[0];
    float4 vq = Vst[0];

    for (int t = 0; t < 16; ++t) {
        float* sk = skb[t & 1];
        float* sv = svb[t & 1];

        // elu + ksum + stage k; stage v pre-duplicated
        float e0 = elu1(kq.x), e1 = elu1(kq.y), e2 = elu1(kq.z), e3 = elu1(kq.w);
        ksum4.x += e0; ksum4.y += e1; ksum4.z += e2; ksum4.w += e3;
        *(float4*)&sk[tok_slot * KROWF + quad * 4] = make_float4(e0, e1, e2, e3);
        *(float4*)&sv[tok_slot * VROWF + quad * 12]     = make_float4(vq.x, vq.x, vq.y, vq.y);
        *(float4*)&sv[tok_slot * VROWF + quad * 12 + 4] = make_float4(vq.z, vq.z, vq.w, vq.w);
        gbar(1 + g);

        if (t + 1 < 16) {                 // prefetch next stage
            kq = Kst[(size_t)(t + 1) * 512];
            vq = Vst[(size_t)(t + 1) * 512];
        }

        #pragma unroll
        for (int s = 0; s < 8; ++s) {
            const ulonglong2 k4 = *(const ulonglong2*)&sk[s * KROWF + ti * 4];
            const float* vrow = &sv[s * VROWF + tj * 12];
            u64 vd0 = *(const u64*)(vrow + 0);
            u64 vd1 = *(const u64*)(vrow + 2);
            u64 vd2 = *(const u64*)(vrow + 4);
            u64 vd3 = *(const u64*)(vrow + 6);
            acc[0][0] = fma2(k4.x, vd0, acc[0][0]);
            acc[1][0] = fma2(k4.y, vd0, acc[1][0]);
            acc[0][1] = fma2(k4.x, vd1, acc[0][1]);
            acc[1][1] = fma2(k4.y, vd1, acc[1][1]);
            acc[0][2] = fma2(k4.x, vd2, acc[0][2]);
            acc[1][2] = fma2(k4.y, vd2, acc[1][2]);
            acc[0][3] = fma2(k4.x, vd3, acc[0][3]);
            acc[1][3] = fma2(k4.y, vd3, acc[1][3]);
        }
        // double-buffered: one barrier per stage is sufficient
    }

    float* gp = g_part + ((size_t)chunk * NH + nh) * PART;

    // KV tile: thread (ti,tj) covers d-pairs jj = 2ti+p, v = 4tj+vj
    #pragma unroll
    for (int p = 0; p < 2; p++) {
        const int fb = (2 * ti + p) * 64 + 8 * tj;   // float index, 32B aligned
        ulonglong2 s0; s0.x = acc[p][0]; s0.y = acc[p][1];
        ulonglong2 s1; s1.x = acc[p][2]; s1.y = acc[p][3];
        *(ulonglong2*)&gp[fb]     = s0;
        *(ulonglong2*)&gp[fb + 4] = s1;
    }

    // Ksum reduce: thread's ksum4 covers d = 4*quad.., tokens == tok_slot slot
    gbar(1 + g);                          // all compute done before smem reuse
    *(float4*)&sm[g64 * 4] = ksum4;
    gbar(1 + g);
    if (g64 < 32) {
        const int d = g64, q = d >> 2, e = d & 3;
        float s = 0.f;
        #pragma unroll
        for (int ts = 0; ts < 8; ts++) s += sm[(ts * 8 + q) * 4 + e];
        gp[1024 + d] = s;
    }
}

// ---------------------------------------------------------------------------
// Mid: reduce 64 chunk partials per head. One thread per (nh, f) element.
// ---------------------------------------------------------------------------
__global__ void __launch_bounds__(256)
reduce_kernel()
{
    const int g = blockIdx.x * 256 + threadIdx.x;   // 0 .. 64*1056-1
    if (g >= NH * PART) return;
    const int nh = g / PART, f = g - nh * PART;
    float s = 0.f;
    #pragma unroll 8
    for (int c = 0; c < P1CH; c++)
        s += g_part[((size_t)c * NH + nh) * PART + f];
    g_red[(size_t)nh * PART + f] = s;
}

// ---------------------------------------------------------------------------
// Phase 2 (unchanged from R10): out = phi(Q) @ KV / (phi(Q).Ksum + eps).
// ---------------------------------------------------------------------------
__global__ void __launch_bounds__(256)
phase2_kernel(const float* __restrict__ Q, float* __restrict__ out)
{
    __shared__ __align__(16) float qbuf[8][8][32];

    const int tid = threadIdx.x;
    const int w = tid >> 5, lane = tid & 31;
    const int nh = blockIdx.x, chunk = blockIdx.y;   // 64 x 16
    const int n = nh >> 3, h = nh & 7;

    const float* red = g_red + (size_t)nh * PART;
    u64 kv[16];
    #pragma unroll
    for (int j = 0; j < 16; j++)
        kv[j] = *(const u64*)&red[j * 64 + lane * 2];
    const float ks = red[1024 + lane];

    const size_t base = ((size_t)n * LL + (size_t)chunk * 512 + w * 64) * RS + h * 32 + lane;
    const float* Qp = Q + base;
    float*       Op = out + base;

    float qr[8];
    #pragma unroll
    for (int i = 0; i < 8; i++) qr[i] = Qp[(size_t)i * RS];

    for (int g = 0; g < 8; ++g) {
        float t[8];
        #pragma unroll
        for (int i = 0; i < 8; i++) {
            float qf = elu1(qr[i]);
            qbuf[w][i][lane] = qf;
            t[i] = qf * ks;
        }
        __syncwarp();

        if (g + 1 < 8) {
            const float* Qn = Qp + (size_t)(g + 1) * 8 * RS;
            #pragma unroll
            for (int i = 0; i < 8; i++) qr[i] = Qn[(size_t)i * RS];
        }

        u64 a[8];
        #pragma unroll
        for (int i = 0; i < 8; i++) a[i] = 0ULL;
        #pragma unroll
        for (int j = 0; j < 8; j++) {
            #pragma unroll
            for (int i = 0; i < 8; i++) {
                ulonglong2 qq = *((const ulonglong2*)qbuf[w][i] + j);
                a[i] = fma2(qq.x, kv[2 * j + 0], a[i]);
                a[i] = fma2(qq.y, kv[2 * j + 1], a[i]);
            }
        }

        #pragma unroll
        for (int m = 16; m >= 1; m >>= 1) {
            #pragma unroll
            for (int i = 0; i < 8; i++)
                t[i] += __shfl_xor_sync(0xFFFFFFFFu, t[i], m);
        }

        #pragma unroll
        for (int i = 0; i < 8; i++) {
            float2 u = unp(a[i]);
            Op[(size_t)(g * 8 + i) * RS] = (u.x + u.y) * __fdividef(1.f, t[i] + 1e-6f);
        }
        __syncwarp();
    }
}

extern "C" void kernel_launch(void* const* d_in, const int* in_sizes, int n_in,
                              void* d_out, int out_size)
{
    const float* queries = (const float*)d_in[0];
    const float* keys    = (const float*)d_in[1];
    const float* values  = (const float*)d_in[2];
    float* out = (float*)d_out;

    phase1_kernel<<<NH * 16, 256>>>(keys, values);
    reduce_kernel<<<(NH * PART + 255) / 256, 256>>>();
    phase2_kernel<<<dim3(NH, P2C), 256>>>(queries, out);
}

// round 14
// speedup vs baseline: 1.1386x; 1.1386x over previous
#include <cuda_runtime.h>
#include <cuda_bf16.h>

// Shape fixed for this dataset entry
#define NN 8
#define LL 8192
#define SS 8192
#define HH 8
#define RS 256              // floats per token row (H*D)
#define NH 64               // N*H

#define P1CH 64             // phase1 chunks per head
#define P1TOK 128           // tokens per warp-chunk
#define P1TILE 8            // tokens per pipeline stage (R5 measured-best)
#define P1NT (P1TOK/P1TILE) // 16 stages
#define PART 1056           // 1024 KV (f32x2-pair layout) + 32 Ksum

#define P2C 16              // phase2 L-chunks

// Deterministic scratch
__device__ __align__(16) float g_part[P1CH * NH * PART];   // ~17.3 MB
__device__ __align__(16) float g_red [NH * PART];          // reduced states

typedef unsigned long long u64;

__device__ __forceinline__ u64 fma2(u64 a, u64 b, u64 c) {
    u64 d;
    asm("fma.rn.f32x2 %0, %1, %2, %3;" : "=l"(d) : "l"(a), "l"(b), "l"(c));
    return d;
}
__device__ __forceinline__ u64 dup2(float v) {
    u64 d;
    asm("mov.b64 %0, {%1, %1};" : "=l"(d) : "f"(v));
    return d;
}
__device__ __forceinline__ float2 unp(u64 a) {
    float2 r;
    asm("mov.b64 {%0, %1}, %2;" : "=f"(r.x), "=f"(r.y) : "l"(a));
    return r;
}
__device__ __forceinline__ float elu1(float x) {
    return x > 0.0f ? x + 1.0f : __expf(x);   // elu(x)+1 = exp(x) for x<=0
}

// ---------------------------------------------------------------------------
// Phase 1 (R5 measured-best, 48.3us): each WARP owns a full 32x32 KV
// accumulator (f32x2 pairs, lane = v column) for a private 128-token chunk.
// elu(K) staged through warp-private smem (syncwarp only), V in registers.
// 8 K + 8 V rows prefetched per stage. Epilogue: coalesced STG.64.
// Partial layout: p = j*64 + 2v + e  <->  KV[2j+e][v];  p=1024+d -> Ksum[d].
// ---------------------------------------------------------------------------
__global__ void __launch_bounds__(256)
phase1_kernel(const float* __restrict__ K, const float* __restrict__ V)
{
    __shared__ __align__(16) float sK[8][P1TILE * 32];   // per-warp stage

    const int tid = threadIdx.x;
    const int w = tid >> 5, lane = tid & 31;
    const int W = blockIdx.x * 8 + w;        // global warp id, 0..4095
    const int nh = W >> 6, chunk = W & (P1CH - 1);
    const int n = nh >> 3, h = nh & 7;

    const size_t tokbase = ((size_t)n * SS + (size_t)chunk * P1TOK) * RS + h * 32 + lane;
    const float* Kp = K + tokbase;
    const float* Vp = V + tokbase;
    float* sk = &sK[w][0];

    u64 acc[16];
    #pragma unroll
    for (int j = 0; j < 16; j++) acc[j] = 0ULL;
    float ksum = 0.f;

    float kr[P1TILE], vr[P1TILE];
    #pragma unroll
    for (int i = 0; i < P1TILE; i++) {       // prefetch stage 0
        kr[i] = Kp[(size_t)i * RS];
        vr[i] = Vp[(size_t)i * RS];
    }

    for (int t = 0; t < P1NT; ++t) {
        float vcur[P1TILE];
        #pragma unroll
        for (int i = 0; i < P1TILE; i++) {
            float e = elu1(kr[i]);
            ksum += e;
            sk[i * 32 + lane] = e;
            vcur[i] = vr[i];
        }
        __syncwarp();

        if (t + 1 < P1NT) {                  // prefetch next stage (front-batched)
            const float* Kn = Kp + (size_t)(t + 1) * P1TILE * RS;
            const float* Vn = Vp + (size_t)(t + 1) * P1TILE * RS;
            #pragma unroll
            for (int i = 0; i < P1TILE; i++) kr[i] = Kn[(size_t)i * RS];
            #pragma unroll
            for (int i = 0; i < P1TILE; i++) vr[i] = Vn[(size_t)i * RS];
        }

        #pragma unroll
        for (int i = 0; i < P1TILE; i++) {
            u64 v2 = dup2(vcur[i]);
            const u64* k2 = (const u64*)(sk + i * 32);   // broadcast LDS.64
            #pragma unroll
            for (int j = 0; j < 16; j++) acc[j] = fma2(k2[j], v2, acc[j]);
        }
        __syncwarp();
    }

    float* gp = g_part + ((size_t)chunk * NH + nh) * PART;
    #pragma unroll
    for (int j = 0; j < 16; j++)             // coalesced 256B STG.64 per j
        *(u64*)&gp[j * 64 + lane * 2] = acc[j];
    gp[1024 + lane] = ksum;
}

// ---------------------------------------------------------------------------
// Mid: reduce 64 chunk partials per head. One thread per (nh, f) element.
// ---------------------------------------------------------------------------
__global__ void __launch_bounds__(256)
reduce_kernel()
{
    const int g = blockIdx.x * 256 + threadIdx.x;   // 0 .. 64*1056-1
    if (g >= NH * PART) return;
    const int nh = g / PART, f = g - nh * PART;
    float s = 0.f;
    #pragma unroll 8
    for (int c = 0; c < P1CH; c++)
        s += g_part[((size_t)c * NH + nh) * PART + f];
    g_red[(size_t)nh * PART + f] = s;
}

// ---------------------------------------------------------------------------
// Phase 2 (R10 measured, ~55us): out = phi(Q) @ KV / (phi(Q).Ksum + eps).
// Lane holds KV column `lane` as 16 packed pairs (from g_red). 8 rows per
// pipeline stage; q broadcast via LDS.128; Z-seed folded into elu step;
// 8 interleaved shuffle butterflies. Warp-private, no block syncs.
// ---------------------------------------------------------------------------
__global__ void __launch_bounds__(256)
phase2_kernel(const float* __restrict__ Q, float* __restrict__ out)
{
    __shared__ __align__(16) float qbuf[8][8][32];

    const int tid = threadIdx.x;
    const int w = tid >> 5, lane = tid & 31;
    const int nh = blockIdx.x, chunk = blockIdx.y;   // 64 x 16
    const int n = nh >> 3, h = nh & 7;

    const float* red = g_red + (size_t)nh * PART;
    u64 kv[16];
    #pragma unroll
    for (int j = 0; j < 16; j++)
        kv[j] = *(const u64*)&red[j * 64 + lane * 2];
    const float ks = red[1024 + lane];

    const size_t base = ((size_t)n * LL + (size_t)chunk * 512 + w * 64) * RS + h * 32 + lane;
    const float* Qp = Q + base;
    float*       Op = out + base;

    float qr[8];
    #pragma unroll
    for (int i = 0; i < 8; i++) qr[i] = Qp[(size_t)i * RS];

    for (int g = 0; g < 8; ++g) {
        float t[8];
        #pragma unroll
        for (int i = 0; i < 8; i++) {        // elu + stage + Z-seed (qf not kept)
            float qf = elu1(qr[i]);
            qbuf[w][i][lane] = qf;
            t[i] = qf * ks;
        }
        __syncwarp();

        if (g + 1 < 8) {                     // prefetch next 8 rows
            const float* Qn = Qp + (size_t)(g + 1) * 8 * RS;
            #pragma unroll
            for (int i = 0; i < 8; i++) qr[i] = Qn[(size_t)i * RS];
        }

        u64 a[8];
        #pragma unroll
        for (int i = 0; i < 8; i++) a[i] = 0ULL;
        #pragma unroll
        for (int j = 0; j < 8; j++) {
            #pragma unroll
            for (int i = 0; i < 8; i++) {    // LDS.128 bcast, 8 indep chains
                ulonglong2 qq = *((const ulonglong2*)qbuf[w][i] + j);
                a[i] = fma2(qq.x, kv[2 * j + 0], a[i]);
                a[i] = fma2(qq.y, kv[2 * j + 1], a[i]);
            }
        }

        #pragma unroll
        for (int m = 16; m >= 1; m >>= 1) {  // 8 interleaved butterflies
            #pragma unroll
            for (int i = 0; i < 8; i++)
                t[i] += __shfl_xor_sync(0xFFFFFFFFu, t[i], m);
        }

        #pragma unroll
        for (int i = 0; i < 8; i++) {
            float2 u = unp(a[i]);
            Op[(size_t)(g * 8 + i) * RS] = (u.x + u.y) * __fdividef(1.f, t[i] + 1e-6f);
        }
        __syncwarp();
    }
}

extern "C" void kernel_launch(void* const* d_in, const int* in_sizes, int n_in,
                              void* d_out, int out_size)
{
    const float* queries = (const float*)d_in[0];
    const float* keys    = (const float*)d_in[1];
    const float* values  = (const float*)d_in[2];
    float* out = (float*)d_out;

    phase1_kernel<<<NH * P1CH / 8, 256>>>(keys, values);
    reduce_kernel<<<(NH * PART + 255) / 256, 256>>>();
    phase2_kernel<<<dim3(NH, P2C), 256>>>(queries, out);
}